// round 14
// baseline (speedup 1.0000x reference)
#include <cuda_runtime.h>
#include <cstdint>
#include <cstddef>

// ExpertGather, sm_103 baseline ISA. out[b,e,k,j] = sum_i x[b,Ind[b,e,k],i]*W[e,i,j]
// B=8 T=8192 I=512 E=16 K=1024 J=512, fp32.
//
// tf32 mma.sync.m16n8k8 + ldmatrix.x4.b16 + 3-stage cp.async, SW128 swizzle.
// R13: R10 structure (wait_group 1, post-barrier ks0 fragments, ks double
// buffer) + cp.async issue burst DISTRIBUTED through the ks-loop mma stream
// (A chunks after fm=0 of ks=0, B chunks after fm=1, commit after fm=2), so
// the post-barrier critical path is 8 LDSM only and LDGSTS overlaps mma.
// Warp tile 64x64, 4 warps, CTA 128x128, 2 CTAs/SM.

namespace {
constexpr int Tdim = 8192;
constexpr int Idim = 512;
constexpr int Edim = 16;
constexpr int Ktok = 1024;
constexpr int Jdim = 512;

constexpr int BM = 128;            // tok tile (M)
constexpr int BN = 128;            // j tile (N)
constexpr int NKT = Idim / 32;     // 16 k-tiles (128B rows)
constexpr int NSTAGE = 3;
constexpr int THREADS = 128;

constexpr int A_BYTES = BM * 128;                 // 16KB
constexpr int B_BYTES = BN * 128;                 // 16KB
constexpr int STAGE_BYTES = A_BYTES + B_BYTES;    // 32KB
constexpr int SMEM_TOTAL = NSTAGE * STAGE_BYTES;  // 98304

__device__ float g_Wt[(size_t)Edim * Jdim * Idim];  // Wt[e][j][i], tf32-rounded

__device__ __forceinline__ uint32_t smem_u32(const void* p) {
    uint32_t a;
    asm("{ .reg .u64 t; cvta.to.shared.u64 t, %1; cvt.u32.u64 %0, t; }" : "=r"(a) : "l"(p));
    return a;
}
__device__ __forceinline__ uint32_t f2tf(float f) {
    uint32_t u;
    asm("cvt.rna.tf32.f32 %0, %1;" : "=r"(u) : "f"(f));
    return u;
}
__device__ __forceinline__ void cp16(uint32_t dst, const void* src) {
    asm volatile("cp.async.cg.shared.global [%0], [%1], 16;" :: "r"(dst), "l"(src) : "memory");
}
__device__ __forceinline__ void cp_commit() {
    asm volatile("cp.async.commit_group;" ::: "memory");
}
__device__ __forceinline__ void cp_wait1() {
    asm volatile("cp.async.wait_group 1;" ::: "memory");
}
__device__ __forceinline__ void ldsm4(uint32_t* r, uint32_t addr) {
    asm volatile("ldmatrix.sync.aligned.m8n8.x4.shared.b16 {%0,%1,%2,%3}, [%4];"
                 : "=r"(r[0]), "=r"(r[1]), "=r"(r[2]), "=r"(r[3]) : "r"(addr));
}
__device__ __forceinline__ void mma8(float* c, const uint32_t* a, uint32_t b0, uint32_t b1) {
    asm volatile(
        "mma.sync.aligned.m16n8k8.row.col.f32.tf32.tf32.f32 "
        "{%0,%1,%2,%3}, {%4,%5,%6,%7}, {%8,%9}, {%0,%1,%2,%3};\n"
        : "+f"(c[0]), "+f"(c[1]), "+f"(c[2]), "+f"(c[3])
        : "r"(a[0]), "r"(a[1]), "r"(a[2]), "r"(a[3]), "r"(b0), "r"(b1));
}
}  // namespace

// ---- W[e][i][j] -> Wt[e][j][i], rounded to tf32 (RNA) ----
__global__ void transpose_w(const float* __restrict__ W) {
    __shared__ float tile[32][33];
    const int e = blockIdx.z;
    const int i0 = blockIdx.x * 32, j0 = blockIdx.y * 32;
    const float* Wp = W + (size_t)e * Idim * Jdim;
    float* Wtp = g_Wt + (size_t)e * Jdim * Idim;
    const int tx = threadIdx.x, ty = threadIdx.y;  // (32,8)
    #pragma unroll
    for (int r = 0; r < 32; r += 8)
        tile[ty + r][tx] = Wp[(size_t)(i0 + ty + r) * Jdim + j0 + tx];
    __syncthreads();
    #pragma unroll
    for (int r = 0; r < 32; r += 8)
        Wtp[(size_t)(j0 + ty + r) * Idim + i0 + tx] =
            __uint_as_float(f2tf(tile[tx][ty + r]));
}

// ---- fused gather + GEMM ----
extern __shared__ __align__(1024) unsigned char smem_raw[];

__global__ __launch_bounds__(THREADS, 2) void eg_mma(
    const float* __restrict__ x,     // [B, T, I]
    const int*   __restrict__ Ind,   // [B, E, K]
    float*       __restrict__ out)   // [B, E, K, J]
{
    const uint32_t sb = smem_u32(smem_raw);

    const int be   = blockIdx.z;
    const int b    = be >> 4;
    const int e    = be & 15;
    const int j0   = blockIdx.x * BN;
    const int tok0 = blockIdx.y * BM;

    const int t    = threadIdx.x;
    const int warp = t >> 5;
    const int lane = t & 31;
    const int warp_m = warp & 1;   // 2 x 64 tok
    const int warp_n = warp >> 1;  // 2 x 64 j
    const int grp = lane >> 2;
    const int tig = lane & 3;

    // ---- cp.async assignments: 16B chunks, 128B rows, 128 threads ----
    const int ccol = t & 7;        // 16B col within row
    const int rb   = t >> 3;       // 0..15
    const uint32_t sw16 = (uint32_t)((ccol ^ (rb & 7)) << 4);
    const uint32_t dst_row = (uint32_t)rb * 128 + sw16;

    // A rows rb + 16*i (i=0..7): gathered; 32-bit byte offsets
    const float* xb = x + (size_t)b * Tdim * Idim;
    uint32_t aoff[8];
    #pragma unroll
    for (int i = 0; i < 8; ++i) {
        const int tok = Ind[(size_t)be * Ktok + tok0 + rb + 16 * i];
        aoff[i] = (uint32_t)tok * (Idim * 4) + (uint32_t)ccol * 16;
    }
    const float* bsrc = g_Wt + ((size_t)e * Jdim + j0 + rb) * Idim + ccol * 4;

    // ---- ldmatrix per-lane addressing ----
    const int l7 = lane & 7;
    const uint32_t a_lm = (uint32_t)(warp_m * 64 + ((lane >> 3) & 1) * 8 + l7) * 128;
    const uint32_t akc  = (uint32_t)(lane >> 4);        // 0/1
    const uint32_t b_lm = (uint32_t)(warp_n * 64 + ((lane >> 4) << 3) + l7) * 128;
    const uint32_t bkc  = (uint32_t)((lane >> 3) & 1);  // 0/1

    float acc[4][8][4];
    #pragma unroll
    for (int i = 0; i < 4; ++i)
        #pragma unroll
        for (int j = 0; j < 8; ++j)
            #pragma unroll
            for (int q = 0; q < 4; ++q) acc[i][j][q] = 0.0f;

    auto issue = [&](int s, int kt) {
        const uint32_t as = sb + (uint32_t)(s * STAGE_BYTES) + dst_row;
        const char* xkb = (const char*)(xb + kt * 32);
        #pragma unroll
        for (int i = 0; i < 8; ++i) cp16(as + i * 2048u, xkb + aoff[i]);
        const uint32_t bs = sb + (uint32_t)(s * STAGE_BYTES + A_BYTES) + dst_row;
        #pragma unroll
        for (int i = 0; i < 8; ++i) cp16(bs + i * 2048u, bsrc + kt * 32 + (size_t)(16 * i) * Idim);
    };

    issue(0, 0); cp_commit();
    issue(1, 1); cp_commit();

    uint32_t af[2][4][4], bf[2][4][4];

    for (int kt = 0; kt < NKT; ++kt) {
        cp_wait1();          // stage kt%3 resident (<=1 group pending)
        __syncthreads();     // publish stage kt; all warps done with stage (kt+2)%3

        const int s = kt % NSTAGE;
        const uint32_t Abase = sb + (uint32_t)(s * STAGE_BYTES) + a_lm;
        const uint32_t Bbase = sb + (uint32_t)(s * STAGE_BYTES + A_BYTES) + b_lm;

        const bool do_issue = (kt + 2 < NKT);
        const int s2 = (kt + 2) % NSTAGE;
        const uint32_t as2 = sb + (uint32_t)(s2 * STAGE_BYTES) + dst_row;
        const uint32_t bs2 = sb + (uint32_t)(s2 * STAGE_BYTES + A_BYTES) + dst_row;
        const char* xkb2 = (const char*)(xb + (kt + 2) * 32);
        const float* bsk2 = bsrc + (kt + 2) * 32;

        // ks=0 fragments: only thing on the post-barrier critical path.
        #pragma unroll
        for (int fm = 0; fm < 4; ++fm)
            ldsm4(af[0][fm], Abase + fm * 2048u + ((akc ^ (uint32_t)l7) << 4));
        #pragma unroll
        for (int p = 0; p < 4; ++p)
            ldsm4(bf[0][p], Bbase + p * 2048u + ((bkc ^ (uint32_t)l7) << 4));

        #pragma unroll
        for (int ks = 0; ks < 4; ++ks) {
            const int cur = ks & 1, nxt = cur ^ 1;
            if (ks < 3) {
                #pragma unroll
                for (int fm = 0; fm < 4; ++fm)
                    ldsm4(af[nxt][fm],
                          Abase + fm * 2048u + (((2u * (ks + 1) + akc) ^ (uint32_t)l7) << 4));
                #pragma unroll
                for (int p = 0; p < 4; ++p)
                    ldsm4(bf[nxt][p],
                          Bbase + p * 2048u + (((2u * (ks + 1) + bkc) ^ (uint32_t)l7) << 4));
            }
            // fm = 0 block
            #pragma unroll
            for (int p = 0; p < 4; ++p) {
                mma8(acc[0][2 * p],     af[cur][0], bf[cur][p][0], bf[cur][p][1]);
                mma8(acc[0][2 * p + 1], af[cur][0], bf[cur][p][2], bf[cur][p][3]);
            }
            if (ks == 0 && do_issue) {
                #pragma unroll
                for (int i = 0; i < 8; ++i) cp16(as2 + i * 2048u, xkb2 + aoff[i]);
            }
            // fm = 1 block
            #pragma unroll
            for (int p = 0; p < 4; ++p) {
                mma8(acc[1][2 * p],     af[cur][1], bf[cur][p][0], bf[cur][p][1]);
                mma8(acc[1][2 * p + 1], af[cur][1], bf[cur][p][2], bf[cur][p][3]);
            }
            if (ks == 1 && do_issue) {
                #pragma unroll
                for (int i = 0; i < 8; ++i)
                    cp16(bs2 + i * 2048u, bsk2 + (size_t)(16 * i) * Idim);
            }
            // fm = 2 block
            #pragma unroll
            for (int p = 0; p < 4; ++p) {
                mma8(acc[2][2 * p],     af[cur][2], bf[cur][p][0], bf[cur][p][1]);
                mma8(acc[2][2 * p + 1], af[cur][2], bf[cur][p][2], bf[cur][p][3]);
            }
            if (ks == 2 && do_issue) cp_commit();
            // fm = 3 block
            #pragma unroll
            for (int p = 0; p < 4; ++p) {
                mma8(acc[3][2 * p],     af[cur][3], bf[cur][p][0], bf[cur][p][1]);
                mma8(acc[3][2 * p + 1], af[cur][3], bf[cur][p][2], bf[cur][p][3]);
            }
        }
    }

    // ---- epilogue ----
    float* ob = out + ((size_t)be * Ktok) * Jdim;
    #pragma unroll
    for (int fm = 0; fm < 4; ++fm) {
        const int r0 = tok0 + warp_m * 64 + fm * 16 + grp;
        #pragma unroll
        for (int fn = 0; fn < 8; ++fn) {
            const int cc = j0 + warp_n * 64 + fn * 8 + 2 * tig;
            *reinterpret_cast<float2*>(ob + (size_t)r0 * Jdim + cc) =
                make_float2(acc[fm][fn][0], acc[fm][fn][1]);
            *reinterpret_cast<float2*>(ob + (size_t)(r0 + 8) * Jdim + cc) =
                make_float2(acc[fm][fn][2], acc[fm][fn][3]);
        }
    }
}

extern "C" void kernel_launch(void* const* d_in, const int* in_sizes, int n_in,
                              void* d_out, int out_size) {
    const float* x   = (const float*)d_in[0];
    const int*   Ind = (const int*)d_in[1];
    const float* W   = (const float*)d_in[2];
    float*       out = (float*)d_out;

    static bool init_done = false;
    if (!init_done) {
        cudaFuncSetAttribute(eg_mma, cudaFuncAttributeMaxDynamicSharedMemorySize,
                             SMEM_TOTAL);
        init_done = true;
    }

    {
        dim3 g(Idim / 32, Jdim / 32, Edim), blk(32, 8);
        transpose_w<<<g, blk>>>(W);
    }
    {
        dim3 g(Jdim / BN, Ktok / BM, 8 * Edim);  // (4, 8, 128)
        eg_mma<<<g, THREADS, SMEM_TOTAL>>>(x, Ind, out);
    }
}

// round 15
// speedup vs baseline: 1.4977x; 1.4977x over previous
#include <cuda_runtime.h>
#include <cuda_fp16.h>
#include <cstdint>
#include <cstddef>

// ExpertGather, sm_103 baseline ISA. out[b,e,k,j] = sum_i x[b,Ind[b,e,k],i]*W[e,i,j]
// B=8 T=8192 I=512 E=16 K=1024 J=512, fp32.
//
// R15: fp16 path. mma.sync.m16n8k16.f16 (2x tf32 rate, same 11-bit significand,
// fp32 accumulate) with prepass conversion: x -> g_xh (fp16), W -> g_Wth
// (transposed [e][j][i], fp16, RNE). Main kernel = R10 pipeline verbatim:
// ldmatrix.x4.b16 fragments, 3-stage cp.async (32KB/stage), SW128 swizzle,
// ks double-buffer, warp tile 64x64, 4 warps, CTA 128x128, 2 CTAs/SM.
// k-tile = 64 halves = 128B rows -> identical byte addressing to the tf32 ver.

namespace {
constexpr int Tdim = 8192;
constexpr int Idim = 512;
constexpr int Edim = 16;
constexpr int Ktok = 1024;
constexpr int Jdim = 512;
constexpr int Bdim = 8;

constexpr int BM = 128;            // tok tile (M)
constexpr int BN = 128;            // j tile (N)
constexpr int NKT = Idim / 64;     // 8 k-tiles of 64 halves (128B rows)
constexpr int NSTAGE = 3;
constexpr int THREADS = 128;

constexpr int A_BYTES = BM * 128;                 // 16KB
constexpr int B_BYTES = BN * 128;                 // 16KB
constexpr int STAGE_BYTES = A_BYTES + B_BYTES;    // 32KB
constexpr int SMEM_TOTAL = NSTAGE * STAGE_BYTES;  // 98304

__device__ __half g_xh[(size_t)Bdim * Tdim * Idim];        // 64MB fp16 x
__device__ __half g_Wth[(size_t)Edim * Jdim * Idim];       // 8MB  fp16 Wt[e][j][i]

__device__ __forceinline__ uint32_t smem_u32(const void* p) {
    uint32_t a;
    asm("{ .reg .u64 t; cvta.to.shared.u64 t, %1; cvt.u32.u64 %0, t; }" : "=r"(a) : "l"(p));
    return a;
}
__device__ __forceinline__ void cp16(uint32_t dst, const void* src) {
    asm volatile("cp.async.cg.shared.global [%0], [%1], 16;" :: "r"(dst), "l"(src) : "memory");
}
__device__ __forceinline__ void cp_commit() {
    asm volatile("cp.async.commit_group;" ::: "memory");
}
__device__ __forceinline__ void cp_wait1() {
    asm volatile("cp.async.wait_group 1;" ::: "memory");
}
__device__ __forceinline__ void ldsm4(uint32_t* r, uint32_t addr) {
    asm volatile("ldmatrix.sync.aligned.m8n8.x4.shared.b16 {%0,%1,%2,%3}, [%4];"
                 : "=r"(r[0]), "=r"(r[1]), "=r"(r[2]), "=r"(r[3]) : "r"(addr));
}
__device__ __forceinline__ void mma16(float* c, const uint32_t* a, uint32_t b0, uint32_t b1) {
    asm volatile(
        "mma.sync.aligned.m16n8k16.row.col.f32.f16.f16.f32 "
        "{%0,%1,%2,%3}, {%4,%5,%6,%7}, {%8,%9}, {%0,%1,%2,%3};\n"
        : "+f"(c[0]), "+f"(c[1]), "+f"(c[2]), "+f"(c[3])
        : "r"(a[0]), "r"(a[1]), "r"(a[2]), "r"(a[3]), "r"(b0), "r"(b1));
}
}  // namespace

// ---- prepass 1: x fp32 -> fp16 (RNE) ----
__global__ void convert_x(const float* __restrict__ x) {
    const size_t i = (size_t)blockIdx.x * blockDim.x + threadIdx.x;  // float4 index
    const float4 v = reinterpret_cast<const float4*>(x)[i];
    __half2* o = reinterpret_cast<__half2*>(g_xh) + 2 * i;
    o[0] = __floats2half2_rn(v.x, v.y);
    o[1] = __floats2half2_rn(v.z, v.w);
}

// ---- prepass 2: W[e][i][j] -> Wth[e][j][i] fp16 (RNE) ----
__global__ void transpose_w(const float* __restrict__ W) {
    __shared__ float tile[32][33];
    const int e = blockIdx.z;
    const int i0 = blockIdx.x * 32, j0 = blockIdx.y * 32;
    const float* Wp = W + (size_t)e * Idim * Jdim;
    __half* Wtp = g_Wth + (size_t)e * Jdim * Idim;
    const int tx = threadIdx.x, ty = threadIdx.y;  // (32,8)
    #pragma unroll
    for (int r = 0; r < 32; r += 8)
        tile[ty + r][tx] = Wp[(size_t)(i0 + ty + r) * Jdim + j0 + tx];
    __syncthreads();
    #pragma unroll
    for (int r = 0; r < 32; r += 8)
        Wtp[(size_t)(j0 + ty + r) * Idim + i0 + tx] = __float2half_rn(tile[tx][ty + r]);
}

// ---- fused gather + GEMM (fp16) ----
extern __shared__ __align__(1024) unsigned char smem_raw[];

__global__ __launch_bounds__(THREADS, 2) void eg_mma(
    const int* __restrict__ Ind,     // [B, E, K]
    float*     __restrict__ out)     // [B, E, K, J]
{
    const uint32_t sb = smem_u32(smem_raw);

    const int be   = blockIdx.z;
    const int b    = be >> 4;
    const int e    = be & 15;
    const int j0   = blockIdx.x * BN;
    const int tok0 = blockIdx.y * BM;

    const int t    = threadIdx.x;
    const int warp = t >> 5;
    const int lane = t & 31;
    const int warp_m = warp & 1;   // 2 x 64 tok
    const int warp_n = warp >> 1;  // 2 x 64 j
    const int grp = lane >> 2;
    const int tig = lane & 3;

    // ---- cp.async assignments: 16B chunks, 128B rows, 128 threads ----
    const int ccol = t & 7;        // 16B col within row
    const int rb   = t >> 3;       // 0..15
    const uint32_t sw16 = (uint32_t)((ccol ^ (rb & 7)) << 4);
    const uint32_t dst_row = (uint32_t)rb * 128 + sw16;

    // A rows rb + 16*i (i=0..7): gathered fp16 rows (1KB each); byte offsets
    const char* xbh = (const char*)(g_xh + (size_t)b * Tdim * Idim);
    uint32_t aoff[8];
    #pragma unroll
    for (int i = 0; i < 8; ++i) {
        const int tok = Ind[(size_t)be * Ktok + tok0 + rb + 16 * i];
        aoff[i] = (uint32_t)tok * (Idim * 2) + (uint32_t)ccol * 16;
    }
    const __half* bsrc = g_Wth + ((size_t)e * Jdim + j0 + rb) * Idim + ccol * 8;

    // ---- ldmatrix per-lane addressing (byte-identical to tf32 version) ----
    const int l7 = lane & 7;
    const uint32_t a_lm = (uint32_t)(warp_m * 64 + ((lane >> 3) & 1) * 8 + l7) * 128;
    const uint32_t akc  = (uint32_t)(lane >> 4);        // 0/1
    const uint32_t b_lm = (uint32_t)(warp_n * 64 + ((lane >> 4) << 3) + l7) * 128;
    const uint32_t bkc  = (uint32_t)((lane >> 3) & 1);  // 0/1

    float acc[4][8][4];
    #pragma unroll
    for (int i = 0; i < 4; ++i)
        #pragma unroll
        for (int j = 0; j < 8; ++j)
            #pragma unroll
            for (int q = 0; q < 4; ++q) acc[i][j][q] = 0.0f;

    auto issue = [&](int s, int kt) {
        const uint32_t as = sb + (uint32_t)(s * STAGE_BYTES) + dst_row;
        const char* xkb = xbh + (size_t)kt * 128;   // k-tile = 64 halves = 128B
        #pragma unroll
        for (int i = 0; i < 8; ++i) cp16(as + i * 2048u, xkb + aoff[i]);
        const uint32_t bs = sb + (uint32_t)(s * STAGE_BYTES + A_BYTES) + dst_row;
        const __half* bk = bsrc + kt * 64;
        #pragma unroll
        for (int i = 0; i < 8; ++i) cp16(bs + i * 2048u, bk + (size_t)(16 * i) * Idim);
    };

    issue(0, 0); cp_commit();
    issue(1, 1); cp_commit();

    uint32_t af[2][4][4], bf[2][4][4];

    for (int kt = 0; kt < NKT; ++kt) {
        cp_wait1();          // stage kt%3 resident (<=1 group pending)
        __syncthreads();     // publish stage kt; all warps done with stage (kt+2)%3

        const int s = kt % NSTAGE;
        const uint32_t Abase = sb + (uint32_t)(s * STAGE_BYTES) + a_lm;
        const uint32_t Bbase = sb + (uint32_t)(s * STAGE_BYTES + A_BYTES) + b_lm;

        // ks=0 fragments first (critical path), then cp.async for kt+2.
        #pragma unroll
        for (int fm = 0; fm < 4; ++fm)
            ldsm4(af[0][fm], Abase + fm * 2048u + ((akc ^ (uint32_t)l7) << 4));
        #pragma unroll
        for (int p = 0; p < 4; ++p)
            ldsm4(bf[0][p], Bbase + p * 2048u + ((bkc ^ (uint32_t)l7) << 4));

        if (kt + 2 < NKT) { issue((kt + 2) % NSTAGE, kt + 2); cp_commit(); }

        #pragma unroll
        for (int ks = 0; ks < 4; ++ks) {   // 4 x k16 per 64-half tile
            const int cur = ks & 1, nxt = cur ^ 1;
            if (ks < 3) {
                #pragma unroll
                for (int fm = 0; fm < 4; ++fm)
                    ldsm4(af[nxt][fm],
                          Abase + fm * 2048u + (((2u * (ks + 1) + akc) ^ (uint32_t)l7) << 4));
                #pragma unroll
                for (int p = 0; p < 4; ++p)
                    ldsm4(bf[nxt][p],
                          Bbase + p * 2048u + (((2u * (ks + 1) + bkc) ^ (uint32_t)l7) << 4));
            }
            #pragma unroll
            for (int fm = 0; fm < 4; ++fm)
                #pragma unroll
                for (int p = 0; p < 4; ++p) {
                    mma16(acc[fm][2 * p],     af[cur][fm], bf[cur][p][0], bf[cur][p][1]);
                    mma16(acc[fm][2 * p + 1], af[cur][fm], bf[cur][p][2], bf[cur][p][3]);
                }
        }
    }

    // ---- epilogue ----
    float* ob = out + ((size_t)be * Ktok) * Jdim;
    #pragma unroll
    for (int fm = 0; fm < 4; ++fm) {
        const int r0 = tok0 + warp_m * 64 + fm * 16 + grp;
        #pragma unroll
        for (int fn = 0; fn < 8; ++fn) {
            const int cc = j0 + warp_n * 64 + fn * 8 + 2 * tig;
            *reinterpret_cast<float2*>(ob + (size_t)r0 * Jdim + cc) =
                make_float2(acc[fm][fn][0], acc[fm][fn][1]);
            *reinterpret_cast<float2*>(ob + (size_t)(r0 + 8) * Jdim + cc) =
                make_float2(acc[fm][fn][2], acc[fm][fn][3]);
        }
    }
}

extern "C" void kernel_launch(void* const* d_in, const int* in_sizes, int n_in,
                              void* d_out, int out_size) {
    const float* x   = (const float*)d_in[0];
    const int*   Ind = (const int*)d_in[1];
    const float* W   = (const float*)d_in[2];
    float*       out = (float*)d_out;

    static bool init_done = false;
    if (!init_done) {
        cudaFuncSetAttribute(eg_mma, cudaFuncAttributeMaxDynamicSharedMemorySize,
                             SMEM_TOTAL);
        init_done = true;
    }

    {   // x -> fp16 (33.5M elements, float4 per thread)
        const size_t n4 = (size_t)Bdim * Tdim * Idim / 4;
        convert_x<<<(unsigned)(n4 / 256), 256>>>(x);
    }
    {   // W -> Wt fp16
        dim3 g(Idim / 32, Jdim / 32, Edim), blk(32, 8);
        transpose_w<<<g, blk>>>(W);
    }
    {
        dim3 g(Jdim / BN, Ktok / BM, Bdim * Edim);  // (4, 8, 128)
        eg_mma<<<g, THREADS, SMEM_TOTAL>>>(Ind, out);
    }
}